// round 5
// baseline (speedup 1.0000x reference)
#include <cuda_runtime.h>

#define EPSLN 1e-5f

// Precomputed per launch (deterministic, graph-capturable)
// B fragments packed per (u, nt, lane) as uint4 covering MMA pair (2u, 2u+1):
//   {b0_c0, b1_c0, b0_c1, b1_c1} = cvt(W[16u+4t+q][8nt+g]), q=0..3
__device__ __align__(16) uint4 g_Wfrag4[4 * 8 * 32];
__device__ __align__(16) float g_ewproj[16];         // We_w @ attn_w[128:192]

__device__ __forceinline__ unsigned cvt_tf32(float x) {
    unsigned r; asm("cvt.rna.tf32.f32 %0, %1;" : "=r"(r) : "f"(x)); return r;
}

#define MMA_TF32(d, a0, a1, a2, a3, b0, b1)                                        \
    asm volatile(                                                                  \
        "mma.sync.aligned.m16n8k8.row.col.f32.tf32.tf32.f32 "                      \
        "{%0,%1,%2,%3},{%4,%5,%6,%7},{%8,%9},{%0,%1,%2,%3};"                       \
        : "+f"(d[0]), "+f"(d[1]), "+f"(d[2]), "+f"(d[3])                           \
        : "r"(a0), "r"(a1), "r"(a2), "r"(a3), "r"(b0), "r"(b1))

// Named barrier over the 64 threads (2 warps) serving one batch
#define BARX(id) asm volatile("bar.sync %0, 64;" :: "r"(id) : "memory")

__global__ void prep_kernel(const float* __restrict__ Ww,
                            const float* __restrict__ Wew,
                            const float* __restrict__ attw) {
    int tid = threadIdx.x;  // 256
    if (tid < 16) {
        float se = 0.f;
#pragma unroll 8
        for (int o = 0; o < 64; ++o) se += Wew[tid * 64 + o] * attw[128 + o];
        g_ewproj[tid] = se;
    }
    // k-permuted B fragments (must match A's gmem-float4 slot mapping)
    for (int idx = tid; idx < 1024; idx += 256) {
        int lane = idx & 31;
        int nt   = (idx >> 5) & 7;
        int u    = idx >> 8;
        int t = lane & 3, g = lane >> 2;
        int kb = u * 16 + 4 * t;
        int n  = nt * 8 + g;
        uint4 v;
        v.x = cvt_tf32(Ww[(kb + 0) * 64 + n]);
        v.y = cvt_tf32(Ww[(kb + 1) * 64 + n]);
        v.z = cvt_tf32(Ww[(kb + 2) * 64 + n]);
        v.w = cvt_tf32(Ww[(kb + 3) * 64 + n]);
        g_Wfrag4[idx] = v;
    }
}

__global__ __launch_bounds__(256, 3) void gat_kernel(
    const float* __restrict__ nodes,
    const float* __restrict__ edges,
    const float* __restrict__ Wbias,
    const float* __restrict__ attw,
    const float* __restrict__ gamma,
    const float* __restrict__ beta,
    float* __restrict__ out)
{
    __shared__ uint4  sB[4 * 8 * 32];        // weight fragments (16 KB)
    __shared__ float4 sStats[4][2][33];      // (sum, sumsq, score, -) per row/half
    __shared__ float  sAttn[4][32];
    __shared__ float2 sT[4][2];              // target LN partials per half

    const int tid  = threadIdx.x;
    const int lane = tid & 31;
    const int warp = tid >> 5;
    const int bl   = warp >> 1;     // batch within CTA (0..3)
    const int half = warp & 1;      // column half (32 cols)
    const int t    = lane & 3;      // threadID-in-group
    const int g    = lane >> 2;     // groupID
    const long long b = (long long)blockIdx.x * 4 + bl;
    const int barid = bl + 1;

    // ---- stage weights (16 KB, once per CTA / 4 batches) ----
    for (int q = tid; q < 1024; q += 256) sB[q] = g_Wfrag4[q];

    // ---- edge score term (half==0 warps, lane = neighbor k) ----
    float ek = 0.f;
    if (half == 0) {
        const float4* er = (const float4*)(edges + (b * 32 + lane) * 16);
#pragma unroll
        for (int e4 = 0; e4 < 4; ++e4) {
            float4 a = er[e4];
            float4 w = *(const float4*)&g_ewproj[e4 * 4];
            ek += a.x * w.x + a.y * w.y + a.z * w.z + a.w * w.w;
        }
    }

    __syncthreads();  // weights staged

    // ---- tensor-core GEMM, A straight from gmem ----
    // rows per lane: m0: g, g+8 ; m1: 16+g, 24+g ; m2: 32 (g==0 only)
    const float* gA = nodes + b * 2112 + 4 * t;   // lane k-base
    float d[3][4][4];
#pragma unroll
    for (int m = 0; m < 3; ++m)
#pragma unroll
        for (int j = 0; j < 4; ++j)
#pragma unroll
            for (int c = 0; c < 4; ++c) d[m][j][c] = 0.f;

#pragma unroll
    for (int u = 0; u < 4; ++u) {
        uint4 bb[4];
#pragma unroll
        for (int j = 0; j < 4; ++j)
            bb[j] = sB[(u * 8 + half * 4 + j) * 32 + lane];

        const float* gu = gA + u * 16;
        float4 f0 = __ldg((const float4*)(gu + (g)      * 64));
        float4 f1 = __ldg((const float4*)(gu + (g + 8)  * 64));
        float4 f2 = __ldg((const float4*)(gu + (16 + g) * 64));
        float4 f3 = __ldg((const float4*)(gu + (24 + g) * 64));
        float4 f4 = (g == 0) ? __ldg((const float4*)(gu + 32 * 64))
                             : make_float4(0.f, 0.f, 0.f, 0.f);

        // m0
        {
            unsigned a0 = cvt_tf32(f0.x), a1 = cvt_tf32(f1.x);
            unsigned a2 = cvt_tf32(f0.y), a3 = cvt_tf32(f1.y);
#pragma unroll
            for (int j = 0; j < 4; ++j) MMA_TF32(d[0][j], a0, a1, a2, a3, bb[j].x, bb[j].y);
            a0 = cvt_tf32(f0.z); a1 = cvt_tf32(f1.z);
            a2 = cvt_tf32(f0.w); a3 = cvt_tf32(f1.w);
#pragma unroll
            for (int j = 0; j < 4; ++j) MMA_TF32(d[0][j], a0, a1, a2, a3, bb[j].z, bb[j].w);
        }
        // m1
        {
            unsigned a0 = cvt_tf32(f2.x), a1 = cvt_tf32(f3.x);
            unsigned a2 = cvt_tf32(f2.y), a3 = cvt_tf32(f3.y);
#pragma unroll
            for (int j = 0; j < 4; ++j) MMA_TF32(d[1][j], a0, a1, a2, a3, bb[j].x, bb[j].y);
            a0 = cvt_tf32(f2.z); a1 = cvt_tf32(f3.z);
            a2 = cvt_tf32(f2.w); a3 = cvt_tf32(f3.w);
#pragma unroll
            for (int j = 0; j < 4; ++j) MMA_TF32(d[1][j], a0, a1, a2, a3, bb[j].z, bb[j].w);
        }
        // m2 (only row 32 real)
        {
            unsigned a0 = cvt_tf32(f4.x), a2 = cvt_tf32(f4.y);
#pragma unroll
            for (int j = 0; j < 4; ++j) MMA_TF32(d[2][j], a0, 0u, a2, 0u, bb[j].x, bb[j].y);
            a0 = cvt_tf32(f4.z); a2 = cvt_tf32(f4.w);
#pragma unroll
            for (int j = 0; j < 4; ++j) MMA_TF32(d[2][j], a0, 0u, a2, 0u, bb[j].z, bb[j].w);
        }
    }

    // ---- epilogue params (post-GEMM to keep mainloop registers lean) ----
    const int col0 = half * 32 + 2 * t;
    float2 wb2[4], aw2[4], g2[4], be2[4];
#pragma unroll
    for (int j = 0; j < 4; ++j) {
        wb2[j] = *(const float2*)(Wbias + col0 + j * 8);
        aw2[j] = *(const float2*)(attw + 64 + col0 + j * 8);
        g2[j]  = *(const float2*)(gamma + col0 + j * 8);
        be2[j] = *(const float2*)(beta  + col0 + j * 8);
    }

    // ---- add bias; per-row stats (sum, sumsq, score) ----
#pragma unroll
    for (int m = 0; m < 3; ++m)
#pragma unroll
        for (int j = 0; j < 4; ++j) {
            d[m][j][0] += wb2[j].x; d[m][j][1] += wb2[j].y;
            d[m][j][2] += wb2[j].x; d[m][j][3] += wb2[j].y;
        }

    float sm[3][2], s2[3][2], sc[3][2];
#pragma unroll
    for (int m = 0; m < 3; ++m)
#pragma unroll
        for (int rh = 0; rh < 2; ++rh) {
            float a = 0.f, q = 0.f, s = 0.f;
#pragma unroll
            for (int j = 0; j < 4; ++j) {
                float h0 = d[m][j][rh * 2], h1 = d[m][j][rh * 2 + 1];
                a += h0 + h1;
                q = fmaf(h0, h0, fmaf(h1, h1, q));
                s = fmaf(h0, aw2[j].x, fmaf(h1, aw2[j].y, s));
            }
#pragma unroll
            for (int dl = 1; dl <= 2; dl <<= 1) {
                a += __shfl_xor_sync(0xffffffffu, a, dl);
                q += __shfl_xor_sync(0xffffffffu, q, dl);
                s += __shfl_xor_sync(0xffffffffu, s, dl);
            }
            sm[m][rh] = a; s2[m][rh] = q; sc[m][rh] = s;
        }
    if (t == 0) {
        sStats[bl][half][g]      = make_float4(sm[0][0], s2[0][0], sc[0][0], 0.f);
        sStats[bl][half][g + 8]  = make_float4(sm[0][1], s2[0][1], sc[0][1], 0.f);
        sStats[bl][half][g + 16] = make_float4(sm[1][0], s2[1][0], sc[1][0], 0.f);
        sStats[bl][half][g + 24] = make_float4(sm[1][1], s2[1][1], sc[1][1], 0.f);
        if (g == 0)
            sStats[bl][half][32] = make_float4(sm[2][0], s2[2][0], sc[2][0], 0.f);
    }
    BARX(barid);   // only this batch's 2 warps

    // ---- layernorm + store for neighbor rows (1..32) ----
    float* gO = out + b * 2112;
#pragma unroll
    for (int m = 0; m < 3; ++m)
#pragma unroll
        for (int rh = 0; rh < 2; ++rh) {
            int row = m * 16 + g + rh * 8;
            bool valid = (row >= 1) && (row <= 32) && !(m == 2 && !(g == 0 && rh == 0));
            if (valid) {
                float4 u0 = sStats[bl][0][row];
                float4 u1 = sStats[bl][1][row];
                float mu  = (u0.x + u1.x) * (1.f / 64.f);
                float var = fmaf(u0.y + u1.y, 1.f / 64.f, -mu * mu);
                float ri  = rsqrtf(var + EPSLN);
#pragma unroll
                for (int j = 0; j < 4; ++j) {
                    float2 o;
                    o.x = fmaf((d[m][j][rh * 2]     - mu) * ri, g2[j].x, be2[j].x);
                    o.y = fmaf((d[m][j][rh * 2 + 1] - mu) * ri, g2[j].y, be2[j].y);
                    *(float2*)(gO + row * 64 + col0 + j * 8) = o;
                }
            }
        }

    // ---- softmax over 32 neighbor scores (half==0 warp of each batch) ----
    if (half == 0) {
        int row = lane + 1;
        float s = sStats[bl][0][row].z + sStats[bl][1][row].z + ek;
        float mx = s;
#pragma unroll
        for (int dl = 16; dl > 0; dl >>= 1) mx = fmaxf(mx, __shfl_xor_sync(0xffffffffu, mx, dl));
        float p = __expf(s - mx);
        float tot = p;
#pragma unroll
        for (int dl = 16; dl > 0; dl >>= 1) tot += __shfl_xor_sync(0xffffffffu, tot, dl);
        sAttn[bl][lane] = p / tot;
    }
    BARX(barid);

    // ---- messages: msg[col] = sum_k attn_k * h_k[col] ----
    float aA = (g > 0) ? sAttn[bl][g - 1] : 0.f;   // row g
    float aB = sAttn[bl][g + 7];                    // row g+8
    float aC = sAttn[bl][g + 15];                   // row 16+g
    float aD = sAttn[bl][g + 23];                   // row 24+g
    float aE = (g == 0) ? sAttn[bl][31] : 0.f;      // row 32

    float pm[4][2];
#pragma unroll
    for (int j = 0; j < 4; ++j)
#pragma unroll
        for (int c = 0; c < 2; ++c) {
            float v = aA * d[0][j][c] + aB * d[0][j][2 + c]
                    + aC * d[1][j][c] + aD * d[1][j][2 + c]
                    + aE * d[2][j][c];
#pragma unroll
            for (int dl = 4; dl <= 16; dl <<= 1)
                v += __shfl_xor_sync(0xffffffffu, v, dl);
            pm[j][c] = v;
        }

    // ---- target row 0 (held by g==0 lanes) ----
    float tv[4][2];
    float tsm = 0.f, ts2 = 0.f;
#pragma unroll
    for (int j = 0; j < 4; ++j)
#pragma unroll
        for (int c = 0; c < 2; ++c) {
            float v = d[0][j][c] + pm[j][c];
            tv[j][c] = v;
            tsm += v;
            ts2 = fmaf(v, v, ts2);
        }
#pragma unroll
    for (int dl = 1; dl <= 2; dl <<= 1) {
        tsm += __shfl_xor_sync(0xffffffffu, tsm, dl);
        ts2 += __shfl_xor_sync(0xffffffffu, ts2, dl);
    }
    if (lane == 0) sT[bl][half] = make_float2(tsm, ts2);
    BARX(barid);

    if (lane < 4) {  // g==0, t=0..3 lanes write target row
        float2 v0 = sT[bl][0], v1 = sT[bl][1];
        float mu  = (v0.x + v1.x) * (1.f / 64.f);
        float var = fmaf(v0.y + v1.y, 1.f / 64.f, -mu * mu);
        float ri  = rsqrtf(var + EPSLN);
#pragma unroll
        for (int j = 0; j < 4; ++j) {
            float2 o;
            o.x = fmaf((tv[j][0] - mu) * ri, g2[j].x, be2[j].x);
            o.y = fmaf((tv[j][1] - mu) * ri, g2[j].y, be2[j].y);
            *(float2*)(gO + col0 + j * 8) = o;
        }
    }
}

extern "C" void kernel_launch(void* const* d_in, const int* in_sizes, int n_in,
                              void* d_out, int out_size) {
    const float* nodes = (const float*)d_in[0];
    const float* edges = (const float*)d_in[1];
    const float* Ww    = (const float*)d_in[2];
    const float* Wb    = (const float*)d_in[3];
    const float* Wew   = (const float*)d_in[4];
    // d_in[5] = We_b   (cancels under softmax shift-invariance)
    const float* attw  = (const float*)d_in[6];
    // d_in[7] = attn_b (cancels under softmax shift-invariance)
    const float* gamma = (const float*)d_in[8];
    const float* beta  = (const float*)d_in[9];

    prep_kernel<<<1, 256>>>(Ww, Wew, attw);
    gat_kernel<<<16384 / 4, 256>>>(nodes, edges, Wb, attw, gamma, beta, (float*)d_out);
}

// round 6
// speedup vs baseline: 1.0569x; 1.0569x over previous
#include <cuda_runtime.h>

#define EPSLN 1e-5f
#define RS 80   // smem row stride in floats (conflict-free for fragment LDS.128)

// Precomputed per launch (deterministic, graph-capturable)
// B fragments packed per (u, nt, lane) as uint4 covering MMA pair (2u, 2u+1):
//   {b0_m0, b1_m0, b0_m1, b1_m1} = cvt(W[16u+4t+q][8nt+g]), q=0..3
__device__ __align__(16) uint4 g_Wfrag4[4 * 8 * 32];
__device__ __align__(16) float g_ewproj[16];         // We_w @ attn_w[128:192]

__device__ __forceinline__ unsigned cvt_tf32(float x) {
    unsigned r; asm("cvt.rna.tf32.f32 %0, %1;" : "=r"(r) : "f"(x)); return r;
}

#define MMA_TF32(d, a0, a1, a2, a3, b0, b1)                                        \
    asm volatile(                                                                  \
        "mma.sync.aligned.m16n8k8.row.col.f32.tf32.tf32.f32 "                      \
        "{%0,%1,%2,%3},{%4,%5,%6,%7},{%8,%9},{%0,%1,%2,%3};"                       \
        : "+f"(d[0]), "+f"(d[1]), "+f"(d[2]), "+f"(d[3])                           \
        : "r"(a0), "r"(a1), "r"(a2), "r"(a3), "r"(b0), "r"(b1))

// Named barrier over the 64 threads (2 warps) serving one batch
#define BARX(id) asm volatile("bar.sync %0, 64;" :: "r"(id) : "memory")

__global__ void prep_kernel(const float* __restrict__ Ww,
                            const float* __restrict__ Wew,
                            const float* __restrict__ attw) {
    int tid = threadIdx.x;  // 256
    if (tid < 16) {
        float se = 0.f;
#pragma unroll 8
        for (int o = 0; o < 64; ++o) se += Wew[tid * 64 + o] * attw[128 + o];
        g_ewproj[tid] = se;
    }
    // k-permuted B fragments (must match A's float4 slot mapping)
    for (int idx = tid; idx < 1024; idx += 256) {
        int lane = idx & 31;
        int nt   = (idx >> 5) & 7;
        int u    = idx >> 8;
        int t = lane & 3, g = lane >> 2;
        int kb = u * 16 + 4 * t;
        int n  = nt * 8 + g;
        uint4 v;
        v.x = cvt_tf32(Ww[(kb + 0) * 64 + n]);
        v.y = cvt_tf32(Ww[(kb + 1) * 64 + n]);
        v.z = cvt_tf32(Ww[(kb + 2) * 64 + n]);
        v.w = cvt_tf32(Ww[(kb + 3) * 64 + n]);
        g_Wfrag4[idx] = v;
    }
}

__global__ __launch_bounds__(256, 3) void gat_kernel(
    const float* __restrict__ nodes,
    const float* __restrict__ edges,
    const float* __restrict__ Wbias,
    const float* __restrict__ attw,
    const float* __restrict__ gamma,
    const float* __restrict__ beta,
    float* __restrict__ out)
{
    __shared__ float  sN[4][33 * RS];        // nodes, pre-rounded to tf32
    __shared__ uint4  sB[4 * 8 * 32];        // weight fragments (16 KB)
    __shared__ float4 sStats[4][2][33];      // (sum, sumsq, score, -) per row/half
    __shared__ float  sAttn[4][32];
    __shared__ float2 sT[4][2];              // target LN partials per half

    const int tid  = threadIdx.x;
    const int lane = tid & 31;
    const int warp = tid >> 5;
    const int bl   = warp >> 1;     // batch within CTA (0..3)
    const int half = warp & 1;      // column half (32 cols)
    const int t    = lane & 3;      // threadID-in-group
    const int g    = lane >> 2;     // groupID
    const long long b = (long long)blockIdx.x * 4 + bl;
    const int barid = bl + 1;

    // ---- stage weights (16 KB, once per CTA / 4 batches) ----
    for (int q = tid; q < 1024; q += 256) sB[q] = g_Wfrag4[q];

    // ---- stage nodes, pre-converted to tf32: 4 batches x 528 float4 ----
    const float* gNall = nodes + (long long)blockIdx.x * 4 * 2112;
#pragma unroll
    for (int bb = 0; bb < 4; ++bb) {
        const float4* src = (const float4*)(gNall + bb * 2112);
#pragma unroll
        for (int qq = 0; qq < 3; ++qq) {
            int q = tid + qq * 256;
            if (q < 528) {
                float4 v = src[q];
                float4 w;
                w.x = __uint_as_float(cvt_tf32(v.x));
                w.y = __uint_as_float(cvt_tf32(v.y));
                w.z = __uint_as_float(cvt_tf32(v.z));
                w.w = __uint_as_float(cvt_tf32(v.w));
                int r = q >> 4, i4 = q & 15;
                *(float4*)&sN[bb][r * RS + i4 * 4] = w;
            }
        }
    }

    // ---- edge score term (half==0 warps, lane = neighbor k) ----
    float ek = 0.f;
    if (half == 0) {
        const float4* er = (const float4*)(edges + (b * 32 + lane) * 16);
#pragma unroll
        for (int e4 = 0; e4 < 4; ++e4) {
            float4 a = er[e4];
            float4 w = *(const float4*)&g_ewproj[e4 * 4];
            ek += a.x * w.x + a.y * w.y + a.z * w.z + a.w * w.w;
        }
    }

    __syncthreads();  // staging complete (CTA-wide, once)

    // ---- tensor-core GEMM, A fragments via LDS.128 (k-permuted slots) ----
    const float* sNb = sN[bl] + g * RS + 4 * t;
    float d[3][4][4];
#pragma unroll
    for (int m = 0; m < 3; ++m)
#pragma unroll
        for (int j = 0; j < 4; ++j)
#pragma unroll
            for (int c = 0; c < 4; ++c) d[m][j][c] = 0.f;

#pragma unroll
    for (int u = 0; u < 4; ++u) {
        uint4 bb[4];
#pragma unroll
        for (int j = 0; j < 4; ++j)
            bb[j] = sB[(u * 8 + half * 4 + j) * 32 + lane];

        const float* su = sNb + u * 16;
        float4 f0 = *(const float4*)(su);                    // row g
        float4 f1 = *(const float4*)(su + 8 * RS);           // row g+8
        float4 f2 = *(const float4*)(su + 16 * RS);          // row 16+g
        float4 f3 = *(const float4*)(su + 24 * RS);          // row 24+g
        float4 f4 = (g == 0) ? *(const float4*)(sN[bl] + 32 * RS + u * 16 + 4 * t)
                             : make_float4(0.f, 0.f, 0.f, 0.f);  // row 32

        // m0
        {
            unsigned a0 = __float_as_uint(f0.x), a1 = __float_as_uint(f1.x);
            unsigned a2 = __float_as_uint(f0.y), a3 = __float_as_uint(f1.y);
#pragma unroll
            for (int j = 0; j < 4; ++j) MMA_TF32(d[0][j], a0, a1, a2, a3, bb[j].x, bb[j].y);
            a0 = __float_as_uint(f0.z); a1 = __float_as_uint(f1.z);
            a2 = __float_as_uint(f0.w); a3 = __float_as_uint(f1.w);
#pragma unroll
            for (int j = 0; j < 4; ++j) MMA_TF32(d[0][j], a0, a1, a2, a3, bb[j].z, bb[j].w);
        }
        // m1
        {
            unsigned a0 = __float_as_uint(f2.x), a1 = __float_as_uint(f3.x);
            unsigned a2 = __float_as_uint(f2.y), a3 = __float_as_uint(f3.y);
#pragma unroll
            for (int j = 0; j < 4; ++j) MMA_TF32(d[1][j], a0, a1, a2, a3, bb[j].x, bb[j].y);
            a0 = __float_as_uint(f2.z); a1 = __float_as_uint(f3.z);
            a2 = __float_as_uint(f2.w); a3 = __float_as_uint(f3.w);
#pragma unroll
            for (int j = 0; j < 4; ++j) MMA_TF32(d[1][j], a0, a1, a2, a3, bb[j].z, bb[j].w);
        }
        // m2 (only row 32 real)
        {
            unsigned a0 = __float_as_uint(f4.x), a2 = __float_as_uint(f4.y);
#pragma unroll
            for (int j = 0; j < 4; ++j) MMA_TF32(d[2][j], a0, 0u, a2, 0u, bb[j].x, bb[j].y);
            a0 = __float_as_uint(f4.z); a2 = __float_as_uint(f4.w);
#pragma unroll
            for (int j = 0; j < 4; ++j) MMA_TF32(d[2][j], a0, 0u, a2, 0u, bb[j].z, bb[j].w);
        }
    }

    // ---- epilogue params (post-GEMM to keep mainloop registers lean) ----
    const int col0 = half * 32 + 2 * t;
    float2 wb2[4], aw2[4], g2[4], be2[4];
#pragma unroll
    for (int j = 0; j < 4; ++j) {
        wb2[j] = *(const float2*)(Wbias + col0 + j * 8);
        aw2[j] = *(const float2*)(attw + 64 + col0 + j * 8);
        g2[j]  = *(const float2*)(gamma + col0 + j * 8);
        be2[j] = *(const float2*)(beta  + col0 + j * 8);
    }

    // ---- add bias; per-row stats (sum, sumsq, score) ----
#pragma unroll
    for (int m = 0; m < 3; ++m)
#pragma unroll
        for (int j = 0; j < 4; ++j) {
            d[m][j][0] += wb2[j].x; d[m][j][1] += wb2[j].y;
            d[m][j][2] += wb2[j].x; d[m][j][3] += wb2[j].y;
        }

    float sm[3][2], s2[3][2], sc[3][2];
#pragma unroll
    for (int m = 0; m < 3; ++m)
#pragma unroll
        for (int rh = 0; rh < 2; ++rh) {
            float a = 0.f, q = 0.f, s = 0.f;
#pragma unroll
            for (int j = 0; j < 4; ++j) {
                float h0 = d[m][j][rh * 2], h1 = d[m][j][rh * 2 + 1];
                a += h0 + h1;
                q = fmaf(h0, h0, fmaf(h1, h1, q));
                s = fmaf(h0, aw2[j].x, fmaf(h1, aw2[j].y, s));
            }
#pragma unroll
            for (int dl = 1; dl <= 2; dl <<= 1) {
                a += __shfl_xor_sync(0xffffffffu, a, dl);
                q += __shfl_xor_sync(0xffffffffu, q, dl);
                s += __shfl_xor_sync(0xffffffffu, s, dl);
            }
            sm[m][rh] = a; s2[m][rh] = q; sc[m][rh] = s;
        }
    if (t == 0) {
        sStats[bl][half][g]      = make_float4(sm[0][0], s2[0][0], sc[0][0], 0.f);
        sStats[bl][half][g + 8]  = make_float4(sm[0][1], s2[0][1], sc[0][1], 0.f);
        sStats[bl][half][g + 16] = make_float4(sm[1][0], s2[1][0], sc[1][0], 0.f);
        sStats[bl][half][g + 24] = make_float4(sm[1][1], s2[1][1], sc[1][1], 0.f);
        if (g == 0)
            sStats[bl][half][32] = make_float4(sm[2][0], s2[2][0], sc[2][0], 0.f);
    }
    BARX(barid);   // only this batch's 2 warps

    // ---- layernorm + store for neighbor rows (1..32) ----
    float* gO = out + b * 2112;
#pragma unroll
    for (int m = 0; m < 3; ++m)
#pragma unroll
        for (int rh = 0; rh < 2; ++rh) {
            int row = m * 16 + g + rh * 8;
            bool valid = (row >= 1) && (row <= 32) && !(m == 2 && !(g == 0 && rh == 0));
            if (valid) {
                float4 u0 = sStats[bl][0][row];
                float4 u1 = sStats[bl][1][row];
                float mu  = (u0.x + u1.x) * (1.f / 64.f);
                float var = fmaf(u0.y + u1.y, 1.f / 64.f, -mu * mu);
                float ri  = rsqrtf(var + EPSLN);
#pragma unroll
                for (int j = 0; j < 4; ++j) {
                    float2 o;
                    o.x = fmaf((d[m][j][rh * 2]     - mu) * ri, g2[j].x, be2[j].x);
                    o.y = fmaf((d[m][j][rh * 2 + 1] - mu) * ri, g2[j].y, be2[j].y);
                    *(float2*)(gO + row * 64 + col0 + j * 8) = o;
                }
            }
        }

    // ---- softmax over 32 neighbor scores (half==0 warp of each batch) ----
    if (half == 0) {
        int row = lane + 1;
        float s = sStats[bl][0][row].z + sStats[bl][1][row].z + ek;
        float mx = s;
#pragma unroll
        for (int dl = 16; dl > 0; dl >>= 1) mx = fmaxf(mx, __shfl_xor_sync(0xffffffffu, mx, dl));
        float p = __expf(s - mx);
        float tot = p;
#pragma unroll
        for (int dl = 16; dl > 0; dl >>= 1) tot += __shfl_xor_sync(0xffffffffu, tot, dl);
        sAttn[bl][lane] = p / tot;
    }
    BARX(barid);

    // ---- messages: msg[col] = sum_k attn_k * h_k[col] ----
    float aA = (g > 0) ? sAttn[bl][g - 1] : 0.f;   // row g
    float aB = sAttn[bl][g + 7];                    // row g+8
    float aC = sAttn[bl][g + 15];                   // row 16+g
    float aD = sAttn[bl][g + 23];                   // row 24+g
    float aE = (g == 0) ? sAttn[bl][31] : 0.f;      // row 32

    float pm[4][2];
#pragma unroll
    for (int j = 0; j < 4; ++j)
#pragma unroll
        for (int c = 0; c < 2; ++c) {
            float v = aA * d[0][j][c] + aB * d[0][j][2 + c]
                    + aC * d[1][j][c] + aD * d[1][j][2 + c]
                    + aE * d[2][j][c];
#pragma unroll
            for (int dl = 4; dl <= 16; dl <<= 1)
                v += __shfl_xor_sync(0xffffffffu, v, dl);
            pm[j][c] = v;
        }

    // ---- target row 0 (held by g==0 lanes) ----
    float tv[4][2];
    float tsm = 0.f, ts2 = 0.f;
#pragma unroll
    for (int j = 0; j < 4; ++j)
#pragma unroll
        for (int c = 0; c < 2; ++c) {
            float v = d[0][j][c] + pm[j][c];
            tv[j][c] = v;
            tsm += v;
            ts2 = fmaf(v, v, ts2);
        }
#pragma unroll
    for (int dl = 1; dl <= 2; dl <<= 1) {
        tsm += __shfl_xor_sync(0xffffffffu, tsm, dl);
        ts2 += __shfl_xor_sync(0xffffffffu, ts2, dl);
    }
    if (lane == 0) sT[bl][half] = make_float2(tsm, ts2);
    BARX(barid);

    if (lane < 4) {  // g==0, t=0..3 lanes write target row
        float2 v0 = sT[bl][0], v1 = sT[bl][1];
        float mu  = (v0.x + v1.x) * (1.f / 64.f);
        float var = fmaf(v0.y + v1.y, 1.f / 64.f, -mu * mu);
        float ri  = rsqrtf(var + EPSLN);
#pragma unroll
        for (int j = 0; j < 4; ++j) {
            float2 o;
            o.x = fmaf((tv[j][0] - mu) * ri, g2[j].x, be2[j].x);
            o.y = fmaf((tv[j][1] - mu) * ri, g2[j].y, be2[j].y);
            *(float2*)(gO + col0 + j * 8) = o;
        }
    }
}

extern "C" void kernel_launch(void* const* d_in, const int* in_sizes, int n_in,
                              void* d_out, int out_size) {
    const float* nodes = (const float*)d_in[0];
    const float* edges = (const float*)d_in[1];
    const float* Ww    = (const float*)d_in[2];
    const float* Wb    = (const float*)d_in[3];
    const float* Wew   = (const float*)d_in[4];
    // d_in[5] = We_b   (cancels under softmax shift-invariance)
    const float* attw  = (const float*)d_in[6];
    // d_in[7] = attn_b (cancels under softmax shift-invariance)
    const float* gamma = (const float*)d_in[8];
    const float* beta  = (const float*)d_in[9];

    prep_kernel<<<1, 256>>>(Ww, Wew, attw);
    gat_kernel<<<16384 / 4, 256>>>(nodes, edges, Wb, attw, gamma, beta, (float*)d_out);
}